// round 1
// baseline (speedup 1.0000x reference)
#include <cuda_runtime.h>
#include <cstddef>

#define NMAX 100000
#define EMAX 3200000
#define CH 128

// Scratch (static __device__ arrays per allocation rules)
__device__ float g_t[(size_t)NMAX * CH];     // t = x @ W_theta^T
__device__ float g_aggr[(size_t)NMAX * CH];  // aggregated features
__device__ int   g_deg[NMAX];
__device__ int   g_off[NMAX + 1];
__device__ int   g_cur[NMAX];
__device__ int   g_csr[EMAX];

__global__ void zero_kernel(int n) {
    int i = blockIdx.x * blockDim.x + threadIdx.x;
    if (i < n) { g_deg[i] = 0; g_cur[i] = 0; }
}

__global__ void count_kernel(const int* __restrict__ row, int E) {
    int e = blockIdx.x * blockDim.x + threadIdx.x;
    if (e < E) atomicAdd(&g_deg[row[e]], 1);
}

// Single-block exclusive scan over g_deg -> g_off (n up to 100k, chunks of 1024)
__global__ void scan_kernel(int n) {
    __shared__ int s[1024];
    int tid = threadIdx.x;
    int carry = 0;
    for (int base = 0; base < n; base += 1024) {
        int i = base + tid;
        int v = (i < n) ? g_deg[i] : 0;
        s[tid] = v;
        __syncthreads();
        #pragma unroll
        for (int d = 1; d < 1024; d <<= 1) {
            int tv = (tid >= d) ? s[tid - d] : 0;
            __syncthreads();
            s[tid] += tv;
            __syncthreads();
        }
        if (i < n) g_off[i] = carry + s[tid] - v;  // exclusive prefix
        carry += s[1023];
        __syncthreads();
    }
    if (tid == 0) g_off[n] = carry;
}

__global__ void scatter_kernel(const int* __restrict__ row, const int* __restrict__ col, int E) {
    int e = blockIdx.x * blockDim.x + threadIdx.x;
    if (e < E) {
        int r = row[e];
        int p = atomicAdd(&g_cur[r], 1);
        g_csr[g_off[r] + p] = col[e];
    }
}

// Cout[M,128] = A[M,128] @ W^T, W[128,128] row-major ([out,in]).
// Block tile 128(M) x 128(N), BK=32, 256 threads, 8x8 micro-tile (strided by 16).
__global__ __launch_bounds__(256) void gemm_kernel(
    const float* __restrict__ A, const float* __restrict__ W,
    float* __restrict__ Cout, int M)
{
    __shared__ float As[32][129];
    __shared__ float Ws[32][129];
    const int tid = threadIdx.x;
    const int tx = tid & 15;
    const int ty = tid >> 4;
    const int m0 = blockIdx.x * 128;

    float acc[8][8];
    #pragma unroll
    for (int i = 0; i < 8; i++)
        #pragma unroll
        for (int j = 0; j < 8; j++) acc[i][j] = 0.f;

    for (int kc = 0; kc < 128; kc += 32) {
        #pragma unroll
        for (int it = 0; it < 4; it++) {
            int q  = tid + it * 256;   // 0..1023
            int r  = q >> 3;           // 0..127 (row of tile)
            int kq = q & 7;            // 0..7   (float4 within 32-k chunk)
            const float4 wv = *reinterpret_cast<const float4*>(W + r * 128 + kc + kq * 4);
            Ws[kq * 4 + 0][r] = wv.x;
            Ws[kq * 4 + 1][r] = wv.y;
            Ws[kq * 4 + 2][r] = wv.z;
            Ws[kq * 4 + 3][r] = wv.w;
            int gm = m0 + r;
            float4 av = make_float4(0.f, 0.f, 0.f, 0.f);
            if (gm < M)
                av = *reinterpret_cast<const float4*>(A + (size_t)gm * 128 + kc + kq * 4);
            As[kq * 4 + 0][r] = av.x;
            As[kq * 4 + 1][r] = av.y;
            As[kq * 4 + 2][r] = av.z;
            As[kq * 4 + 3][r] = av.w;
        }
        __syncthreads();
        #pragma unroll
        for (int k = 0; k < 32; k++) {
            float a[8], b[8];
            #pragma unroll
            for (int i = 0; i < 8; i++) a[i] = As[k][ty + 16 * i];
            #pragma unroll
            for (int j = 0; j < 8; j++) b[j] = Ws[k][tx + 16 * j];
            #pragma unroll
            for (int i = 0; i < 8; i++)
                #pragma unroll
                for (int j = 0; j < 8; j++)
                    acc[i][j] = fmaf(a[i], b[j], acc[i][j]);
        }
        __syncthreads();
    }
    #pragma unroll
    for (int i = 0; i < 8; i++) {
        int gm = m0 + ty + 16 * i;
        if (gm < M) {
            #pragma unroll
            for (int j = 0; j < 8; j++)
                Cout[(size_t)gm * 128 + tx + 16 * j] = acc[i][j];
        }
    }
}

// aggr[n] = t[n] - min_{col in nbr(n)} t[col]   (0 for empty rows)
// One block (128 threads = 4 warps) per node; each warp handles every 4th
// neighbor with a full-row float4 gather (32 lanes x 16B = 512B).
__global__ void aggr_kernel() {
    const int n   = blockIdx.x;
    const int tid = threadIdx.x;
    const int w   = tid >> 5;
    const int l   = tid & 31;
    const int start = g_off[n];
    const int end   = g_off[n + 1];

    __shared__ int   s_col[128];
    __shared__ float s_red[4][128];

    float4 m = make_float4(3.402823466e38f, 3.402823466e38f,
                           3.402823466e38f, 3.402823466e38f);

    for (int base = start; base < end; base += 128) {
        int cnt = min(128, end - base);
        if (tid < cnt) s_col[tid] = g_csr[base + tid];
        __syncthreads();
        for (int i = w; i < cnt; i += 4) {
            const float4 v = *reinterpret_cast<const float4*>(
                g_t + (size_t)s_col[i] * CH + l * 4);
            m.x = fminf(m.x, v.x);
            m.y = fminf(m.y, v.y);
            m.z = fminf(m.z, v.z);
            m.w = fminf(m.w, v.w);
        }
        __syncthreads();
    }

    *reinterpret_cast<float4*>(&s_red[w][l * 4]) = m;
    __syncthreads();

    if (w == 0) {
        float4 r = m;
        #pragma unroll
        for (int ww = 1; ww < 4; ww++) {
            float4 o = *reinterpret_cast<const float4*>(&s_red[ww][l * 4]);
            r.x = fminf(r.x, o.x);
            r.y = fminf(r.y, o.y);
            r.z = fminf(r.z, o.z);
            r.w = fminf(r.w, o.w);
        }
        float4 outv;
        if (start == end) {
            outv = make_float4(0.f, 0.f, 0.f, 0.f);
        } else {
            const float4 tv = *reinterpret_cast<const float4*>(
                g_t + (size_t)n * CH + l * 4);
            outv = make_float4(tv.x - r.x, tv.y - r.y, tv.z - r.z, tv.w - r.w);
        }
        *reinterpret_cast<float4*>(g_aggr + (size_t)n * CH + l * 4) = outv;
    }
}

extern "C" void kernel_launch(void* const* d_in, const int* in_sizes, int n_in,
                              void* d_out, int out_size) {
    const float* x  = (const float*)d_in[0];
    const int*   ei = (const int*)d_in[1];
    const float* Wt = (const float*)d_in[2];
    const float* Wp = (const float*)d_in[3];
    float* out = (float*)d_out;

    int N = in_sizes[0] / CH;
    int E = in_sizes[1] / 2;
    const int* row = ei;
    const int* col = ei + E;

    void *pt = nullptr, *pa = nullptr;
    cudaGetSymbolAddress(&pt, g_t);
    cudaGetSymbolAddress(&pa, g_aggr);

    zero_kernel<<<(N + 255) / 256, 256>>>(N);
    gemm_kernel<<<(N + 127) / 128, 256>>>(x, Wt, (float*)pt, N);
    count_kernel<<<(E + 255) / 256, 256>>>(row, E);
    scan_kernel<<<1, 1024>>>(N);
    scatter_kernel<<<(E + 255) / 256, 256>>>(row, col, E);
    aggr_kernel<<<N, 128>>>();
    gemm_kernel<<<(N + 127) / 128, 256>>>((const float*)pa, Wp, out, N);
}

// round 2
// speedup vs baseline: 1.3203x; 1.3203x over previous
#include <cuda_runtime.h>
#include <cstddef>

#define NMAX 100000
#define EMAX 3200000
#define CH 128
#define SCAN_BLK 1024
#define NBMAX ((NMAX + SCAN_BLK - 1) / SCAN_BLK)   // 98

// Scratch (static __device__ arrays per allocation rules)
__device__ float g_t[(size_t)NMAX * CH];     // t = x @ W_theta^T
__device__ float g_aggr[(size_t)NMAX * CH];  // aggregated features
__device__ int   g_deg[NMAX];
__device__ int   g_off[NMAX + 1];
__device__ int   g_cur[NMAX];
__device__ int   g_csr[EMAX];
__device__ int   g_bsum[NBMAX];
__device__ int   g_boff[NBMAX];

__global__ void zero_kernel(int n) {
    int i = blockIdx.x * blockDim.x + threadIdx.x;
    if (i < n) { g_deg[i] = 0; g_cur[i] = 0; }
}

__global__ void count_kernel(const int* __restrict__ row, int E) {
    int e = blockIdx.x * blockDim.x + threadIdx.x;
    if (e < E) atomicAdd(&g_deg[row[e]], 1);
}

// ---------- 3-phase parallel exclusive scan of g_deg -> g_off ----------

__device__ __forceinline__ int warp_incl_scan(int x, int lane) {
    #pragma unroll
    for (int d = 1; d < 32; d <<= 1) {
        int t = __shfl_up_sync(0xffffffffu, x, d);
        if (lane >= d) x += t;
    }
    return x;
}

// Phase 1: per-block exclusive scan (block-local), block totals to g_bsum.
__global__ __launch_bounds__(SCAN_BLK) void scan_block_kernel(int n) {
    const int tid  = threadIdx.x;
    const int lane = tid & 31;
    const int wid  = tid >> 5;
    const int i    = blockIdx.x * SCAN_BLK + tid;

    int v = (i < n) ? g_deg[i] : 0;
    int incl = warp_incl_scan(v, lane);

    __shared__ int wsum[32];
    if (lane == 31) wsum[wid] = incl;
    __syncthreads();
    if (wid == 0) {
        int y = wsum[lane];
        y = warp_incl_scan(y, lane);
        wsum[lane] = y;
    }
    __syncthreads();

    int excl = incl - v + (wid > 0 ? wsum[wid - 1] : 0);
    if (i < n) g_off[i] = excl;
    if (tid == SCAN_BLK - 1) g_bsum[blockIdx.x] = excl + v;
}

// Phase 2: one block scans the block sums (nb <= 1024); exclusive to g_boff,
// total to g_off[n].
__global__ __launch_bounds__(SCAN_BLK) void scan_top_kernel(int nb, int n) {
    const int tid  = threadIdx.x;
    const int lane = tid & 31;
    const int wid  = tid >> 5;

    int v = (tid < nb) ? g_bsum[tid] : 0;
    int incl = warp_incl_scan(v, lane);

    __shared__ int wsum[32];
    if (lane == 31) wsum[wid] = incl;
    __syncthreads();
    if (wid == 0) {
        int y = wsum[lane];
        y = warp_incl_scan(y, lane);
        wsum[lane] = y;
    }
    __syncthreads();

    int full_incl = incl + (wid > 0 ? wsum[wid - 1] : 0);
    if (tid < nb) g_boff[tid] = full_incl - v;
    if (tid == SCAN_BLK - 1) g_off[n] = full_incl;  // total = E
}

// Phase 3: add block offsets.
__global__ __launch_bounds__(SCAN_BLK) void add_off_kernel(int n) {
    int i = blockIdx.x * SCAN_BLK + threadIdx.x;
    if (i < n) g_off[i] += g_boff[blockIdx.x];
}

// -----------------------------------------------------------------------

__global__ void scatter_kernel(const int* __restrict__ row, const int* __restrict__ col, int E) {
    int e = blockIdx.x * blockDim.x + threadIdx.x;
    if (e < E) {
        int r = row[e];
        int p = atomicAdd(&g_cur[r], 1);
        g_csr[g_off[r] + p] = col[e];
    }
}

// Cout[M,128] = A[M,128] @ W^T, W[128,128] row-major ([out,in]).
// Block tile 128(M) x 128(N), BK=32, 256 threads, 8x8 micro-tile (strided by 16).
__global__ __launch_bounds__(256) void gemm_kernel(
    const float* __restrict__ A, const float* __restrict__ W,
    float* __restrict__ Cout, int M)
{
    __shared__ float As[32][129];
    __shared__ float Ws[32][129];
    const int tid = threadIdx.x;
    const int tx = tid & 15;
    const int ty = tid >> 4;
    const int m0 = blockIdx.x * 128;

    float acc[8][8];
    #pragma unroll
    for (int i = 0; i < 8; i++)
        #pragma unroll
        for (int j = 0; j < 8; j++) acc[i][j] = 0.f;

    for (int kc = 0; kc < 128; kc += 32) {
        #pragma unroll
        for (int it = 0; it < 4; it++) {
            int q  = tid + it * 256;   // 0..1023
            int r  = q >> 3;           // 0..127 (row of tile)
            int kq = q & 7;            // 0..7   (float4 within 32-k chunk)
            const float4 wv = *reinterpret_cast<const float4*>(W + r * 128 + kc + kq * 4);
            Ws[kq * 4 + 0][r] = wv.x;
            Ws[kq * 4 + 1][r] = wv.y;
            Ws[kq * 4 + 2][r] = wv.z;
            Ws[kq * 4 + 3][r] = wv.w;
            int gm = m0 + r;
            float4 av = make_float4(0.f, 0.f, 0.f, 0.f);
            if (gm < M)
                av = *reinterpret_cast<const float4*>(A + (size_t)gm * 128 + kc + kq * 4);
            As[kq * 4 + 0][r] = av.x;
            As[kq * 4 + 1][r] = av.y;
            As[kq * 4 + 2][r] = av.z;
            As[kq * 4 + 3][r] = av.w;
        }
        __syncthreads();
        #pragma unroll
        for (int k = 0; k < 32; k++) {
            float a[8], b[8];
            #pragma unroll
            for (int i = 0; i < 8; i++) a[i] = As[k][ty + 16 * i];
            #pragma unroll
            for (int j = 0; j < 8; j++) b[j] = Ws[k][tx + 16 * j];
            #pragma unroll
            for (int i = 0; i < 8; i++)
                #pragma unroll
                for (int j = 0; j < 8; j++)
                    acc[i][j] = fmaf(a[i], b[j], acc[i][j]);
        }
        __syncthreads();
    }
    #pragma unroll
    for (int i = 0; i < 8; i++) {
        int gm = m0 + ty + 16 * i;
        if (gm < M) {
            #pragma unroll
            for (int j = 0; j < 8; j++)
                Cout[(size_t)gm * 128 + tx + 16 * j] = acc[i][j];
        }
    }
}

// aggr[n] = t[n] - min_{col in nbr(n)} t[col]   (0 for empty rows)
// One block (128 threads = 4 warps) per node; each warp handles every 4th
// neighbor with a full-row float4 gather (32 lanes x 16B = 512B).
__global__ void aggr_kernel() {
    const int n   = blockIdx.x;
    const int tid = threadIdx.x;
    const int w   = tid >> 5;
    const int l   = tid & 31;
    const int start = g_off[n];
    const int end   = g_off[n + 1];

    __shared__ int   s_col[128];
    __shared__ float s_red[4][128];

    float4 m = make_float4(3.402823466e38f, 3.402823466e38f,
                           3.402823466e38f, 3.402823466e38f);

    for (int base = start; base < end; base += 128) {
        int cnt = min(128, end - base);
        if (tid < cnt) s_col[tid] = g_csr[base + tid];
        __syncthreads();
        for (int i = w; i < cnt; i += 4) {
            const float4 v = *reinterpret_cast<const float4*>(
                g_t + (size_t)s_col[i] * CH + l * 4);
            m.x = fminf(m.x, v.x);
            m.y = fminf(m.y, v.y);
            m.z = fminf(m.z, v.z);
            m.w = fminf(m.w, v.w);
        }
        __syncthreads();
    }

    *reinterpret_cast<float4*>(&s_red[w][l * 4]) = m;
    __syncthreads();

    if (w == 0) {
        float4 r = m;
        #pragma unroll
        for (int ww = 1; ww < 4; ww++) {
            float4 o = *reinterpret_cast<const float4*>(&s_red[ww][l * 4]);
            r.x = fminf(r.x, o.x);
            r.y = fminf(r.y, o.y);
            r.z = fminf(r.z, o.z);
            r.w = fminf(r.w, o.w);
        }
        float4 outv;
        if (start == end) {
            outv = make_float4(0.f, 0.f, 0.f, 0.f);
        } else {
            const float4 tv = *reinterpret_cast<const float4*>(
                g_t + (size_t)n * CH + l * 4);
            outv = make_float4(tv.x - r.x, tv.y - r.y, tv.z - r.z, tv.w - r.w);
        }
        *reinterpret_cast<float4*>(g_aggr + (size_t)n * CH + l * 4) = outv;
    }
}

extern "C" void kernel_launch(void* const* d_in, const int* in_sizes, int n_in,
                              void* d_out, int out_size) {
    const float* x  = (const float*)d_in[0];
    const int*   ei = (const int*)d_in[1];
    const float* Wt = (const float*)d_in[2];
    const float* Wp = (const float*)d_in[3];
    float* out = (float*)d_out;

    int N = in_sizes[0] / CH;
    int E = in_sizes[1] / 2;
    const int* row = ei;
    const int* col = ei + E;
    int nb = (N + SCAN_BLK - 1) / SCAN_BLK;

    void *pt = nullptr, *pa = nullptr;
    cudaGetSymbolAddress(&pt, g_t);
    cudaGetSymbolAddress(&pa, g_aggr);

    zero_kernel<<<(N + 255) / 256, 256>>>(N);
    gemm_kernel<<<(N + 127) / 128, 256>>>(x, Wt, (float*)pt, N);
    count_kernel<<<(E + 255) / 256, 256>>>(row, E);
    scan_block_kernel<<<nb, SCAN_BLK>>>(N);
    scan_top_kernel<<<1, SCAN_BLK>>>(nb, N);
    add_off_kernel<<<nb, SCAN_BLK>>>(N);
    scatter_kernel<<<(E + 255) / 256, 256>>>(row, col, E);
    aggr_kernel<<<N, 128>>>();
    gemm_kernel<<<(N + 127) / 128, 256>>>((const float*)pa, Wp, out, N);
}

// round 4
// speedup vs baseline: 1.7379x; 1.3163x over previous
#include <cuda_runtime.h>
#include <cuda_bf16.h>
#include <cstdint>
#include <cstddef>

#define NMAX 100000
#define EMAX 3200000
#define CH 128
#define SCAN_BLK 1024
#define NBMAX ((NMAX + SCAN_BLK - 1) / SCAN_BLK)

// ---------------- scratch ----------------
__device__ float g_t[(size_t)NMAX * CH];
__device__ float g_aggr[(size_t)NMAX * CH];
__device__ int   g_deg[NMAX];
__device__ int   g_off[NMAX + 1];
__device__ int   g_cur[NMAX];
__device__ int   g_csr[EMAX];
__device__ int   g_bsum[NBMAX];
__device__ int   g_boff[NBMAX];
__device__ __nv_bfloat16 g_w_hi[2 * CH * CH];
__device__ __nv_bfloat16 g_w_lo[2 * CH * CH];

// ---------------- small kernels ----------------
__global__ void zero_kernel(int n) {
    int i = blockIdx.x * blockDim.x + threadIdx.x;
    if (i < n) { g_deg[i] = 0; g_cur[i] = 0; }
}

__global__ void conv_w_kernel(const float* __restrict__ Wt, const float* __restrict__ Wp) {
    int i = blockIdx.x * blockDim.x + threadIdx.x;
    if (i < 2 * CH * CH) {
        float v = (i < CH * CH) ? Wt[i] : Wp[i - CH * CH];
        __nv_bfloat16 h = __float2bfloat16_rn(v);
        g_w_hi[i] = h;
        g_w_lo[i] = __float2bfloat16_rn(v - __bfloat162float(h));
    }
}

__global__ void count_kernel(const int* __restrict__ row, int E) {
    int e = blockIdx.x * blockDim.x + threadIdx.x;
    if (e < E) atomicAdd(&g_deg[row[e]], 1);
}

__device__ __forceinline__ int warp_incl_scan(int x, int lane) {
    #pragma unroll
    for (int d = 1; d < 32; d <<= 1) {
        int t = __shfl_up_sync(0xffffffffu, x, d);
        if (lane >= d) x += t;
    }
    return x;
}

__global__ __launch_bounds__(SCAN_BLK) void scan_block_kernel(int n) {
    const int tid = threadIdx.x, lane = tid & 31, wid = tid >> 5;
    const int i = blockIdx.x * SCAN_BLK + tid;
    int v = (i < n) ? g_deg[i] : 0;
    int incl = warp_incl_scan(v, lane);
    __shared__ int wsum[32];
    if (lane == 31) wsum[wid] = incl;
    __syncthreads();
    if (wid == 0) wsum[lane] = warp_incl_scan(wsum[lane], lane);
    __syncthreads();
    int excl = incl - v + (wid > 0 ? wsum[wid - 1] : 0);
    if (i < n) g_off[i] = excl;
    if (tid == SCAN_BLK - 1) g_bsum[blockIdx.x] = excl + v;
}

__global__ __launch_bounds__(SCAN_BLK) void scan_top_kernel(int nb, int n) {
    const int tid = threadIdx.x, lane = tid & 31, wid = tid >> 5;
    int v = (tid < nb) ? g_bsum[tid] : 0;
    int incl = warp_incl_scan(v, lane);
    __shared__ int wsum[32];
    if (lane == 31) wsum[wid] = incl;
    __syncthreads();
    if (wid == 0) wsum[lane] = warp_incl_scan(wsum[lane], lane);
    __syncthreads();
    int full_incl = incl + (wid > 0 ? wsum[wid - 1] : 0);
    if (tid < nb) g_boff[tid] = full_incl - v;
    if (tid == SCAN_BLK - 1) g_off[n] = full_incl;
}

__global__ __launch_bounds__(SCAN_BLK) void add_off_kernel(int n) {
    int i = blockIdx.x * SCAN_BLK + threadIdx.x;
    if (i < n) g_off[i] += g_boff[blockIdx.x];
}

__global__ void scatter_kernel(const int* __restrict__ row, const int* __restrict__ col, int E) {
    int e = blockIdx.x * blockDim.x + threadIdx.x;
    if (e < E) {
        int r = row[e];
        int p = atomicAdd(&g_cur[r], 1);
        g_csr[g_off[r] + p] = col[e];
    }
}

// ---------------- HMMA (mma.sync) helpers ----------------
__device__ __forceinline__ uint32_t smem_u32(const void* p) {
    uint32_t a;
    asm("{ .reg .u64 t; cvta.to.shared.u64 t, %1; cvt.u32.u64 %0, t; }" : "=r"(a) : "l"(p));
    return a;
}

__device__ __forceinline__ void ldsm_x4(uint32_t addr, uint32_t& r0, uint32_t& r1,
                                        uint32_t& r2, uint32_t& r3) {
    asm volatile("ldmatrix.sync.aligned.m8n8.x4.shared.b16 {%0,%1,%2,%3}, [%4];"
                 : "=r"(r0), "=r"(r1), "=r"(r2), "=r"(r3) : "r"(addr));
}

__device__ __forceinline__ void mma_bf16(float* c, const uint32_t* a, const uint32_t* b) {
    asm volatile(
        "mma.sync.aligned.m16n8k16.row.col.f32.bf16.bf16.f32 "
        "{%0,%1,%2,%3}, {%4,%5,%6,%7}, {%8,%9}, {%0,%1,%2,%3};"
        : "+f"(c[0]), "+f"(c[1]), "+f"(c[2]), "+f"(c[3])
        : "r"(a[0]), "r"(a[1]), "r"(a[2]), "r"(a[3]), "r"(b[0]), "r"(b[1]));
}

// ---------------- tensor-core GEMM: C[M,128] = A[M,128] @ W^T ----------------
// bf16 hi/lo split, 3 accumulating passes: Ahi*Whi + Ahi*Wlo + Alo*Whi.
// SMEM rows padded to 272B (136 bf16) for conflict-free ldmatrix.
#define ROWB 272
#define TILEB (128 * ROWB)         // 34816
#define AS_HI 0
#define AS_LO TILEB
#define WS_HI (2 * TILEB)
#define WS_LO (3 * TILEB)
#define GSM_TOTAL (4 * TILEB)      // 139264

__global__ __launch_bounds__(256) void tc_gemm_kernel(
    const float* __restrict__ A, float* __restrict__ C, int M, int which)
{
    extern __shared__ char smem[];
    const uint32_t sb = smem_u32(smem);
    const int tid = threadIdx.x;
    const int w = tid >> 5;
    const int lane = tid & 31;
    const int m0 = blockIdx.x * 128;

    // ---- stage A: fp32 -> bf16 hi/lo ----
    #pragma unroll
    for (int it = 0; it < 16; it++) {
        int q = tid + it * 256;          // 0..4095 float4s
        int r = q >> 5;                  // row 0..127
        int c4 = q & 31;                 // float4 within row
        int gm = m0 + r;
        float4 v = make_float4(0.f, 0.f, 0.f, 0.f);
        if (gm < M) v = *reinterpret_cast<const float4*>(A + (size_t)gm * CH + c4 * 4);

        __nv_bfloat16 h0 = __float2bfloat16_rn(v.x);
        __nv_bfloat16 h1 = __float2bfloat16_rn(v.y);
        __nv_bfloat16 h2 = __float2bfloat16_rn(v.z);
        __nv_bfloat16 h3 = __float2bfloat16_rn(v.w);
        __nv_bfloat16 l0 = __float2bfloat16_rn(v.x - __bfloat162float(h0));
        __nv_bfloat16 l1 = __float2bfloat16_rn(v.y - __bfloat162float(h1));
        __nv_bfloat16 l2 = __float2bfloat16_rn(v.z - __bfloat162float(h2));
        __nv_bfloat16 l3 = __float2bfloat16_rn(v.w - __bfloat162float(h3));

        uint32_t hw0 = ((uint32_t)__bfloat16_as_ushort(h1) << 16) | __bfloat16_as_ushort(h0);
        uint32_t hw1 = ((uint32_t)__bfloat16_as_ushort(h3) << 16) | __bfloat16_as_ushort(h2);
        uint32_t lw0 = ((uint32_t)__bfloat16_as_ushort(l1) << 16) | __bfloat16_as_ushort(l0);
        uint32_t lw1 = ((uint32_t)__bfloat16_as_ushort(l3) << 16) | __bfloat16_as_ushort(l2);

        int off = r * ROWB + c4 * 8;
        *reinterpret_cast<uint2*>(smem + AS_HI + off) = make_uint2(hw0, hw1);
        *reinterpret_cast<uint2*>(smem + AS_LO + off) = make_uint2(lw0, lw1);
    }

    // ---- stage W hi/lo (already bf16 in global) ----
    const uint4* whi = reinterpret_cast<const uint4*>(g_w_hi + (size_t)which * CH * CH);
    const uint4* wlo = reinterpret_cast<const uint4*>(g_w_lo + (size_t)which * CH * CH);
    #pragma unroll
    for (int it = 0; it < 8; it++) {
        int q = tid + it * 256;          // 0..2047 uint4s (16 rows of 16 uint4)
        int r = q >> 4;                  // row (n)
        int u = q & 15;                  // uint4 within row
        int off = r * ROWB + u * 16;
        *reinterpret_cast<uint4*>(smem + WS_HI + off) = whi[q];
        *reinterpret_cast<uint4*>(smem + WS_LO + off) = wlo[q];
    }
    __syncthreads();

    // ---- compute: warp grid 4(M) x 2(N); warp tile 32x64 ----
    const int mw0 = (w & 3) * 32;
    const int nw0 = (w >> 2) * 64;

    float acc[2][8][4];
    #pragma unroll
    for (int i = 0; i < 2; i++)
        #pragma unroll
        for (int j = 0; j < 8; j++)
            #pragma unroll
            for (int q = 0; q < 4; q++) acc[i][j][q] = 0.f;

    // per-lane ldmatrix byte offsets (k0 added in loop)
    const int a_row = mw0 + (lane & 15);
    const int a_kof = (lane >> 4) * 8;               // 0 or 8
    const int b_nof = (lane & 7) + ((lane >> 4) ? 8 : 0);
    const int b_kof = ((lane >> 3) & 1) * 8;

    const uint32_t a_base0 = sb + a_row * ROWB + a_kof * 2;
    const uint32_t b_base0 = sb + (nw0 + b_nof) * ROWB + b_kof * 2;

    #pragma unroll
    for (int pass = 0; pass < 3; pass++) {
        const uint32_t a_base = a_base0 + ((pass < 2) ? AS_HI : AS_LO);
        const uint32_t b_base = b_base0 + ((pass == 1) ? WS_LO : WS_HI);
        #pragma unroll
        for (int ks = 0; ks < 8; ks++) {
            const int k0 = ks * 16;
            uint32_t af[2][4];
            ldsm_x4(a_base + k0 * 2,            af[0][0], af[0][1], af[0][2], af[0][3]);
            ldsm_x4(a_base + 16 * ROWB + k0 * 2, af[1][0], af[1][1], af[1][2], af[1][3]);
            uint32_t bf[8][2];
            #pragma unroll
            for (int p = 0; p < 4; p++) {
                uint32_t r0, r1, r2, r3;
                ldsm_x4(b_base + p * 16 * ROWB + k0 * 2, r0, r1, r2, r3);
                bf[2 * p][0] = r0; bf[2 * p][1] = r1;
                bf[2 * p + 1][0] = r2; bf[2 * p + 1][1] = r3;
            }
            #pragma unroll
            for (int i = 0; i < 2; i++)
                #pragma unroll
                for (int j = 0; j < 8; j++)
                    mma_bf16(acc[i][j], af[i], bf[j]);
        }
    }

    // ---- epilogue ----
    const int mq = lane >> 2;            // 0..7
    const int nq = (lane & 3) * 2;       // 0,2,4,6
    #pragma unroll
    for (int i = 0; i < 2; i++) {
        #pragma unroll
        for (int half = 0; half < 2; half++) {
            int gm = m0 + mw0 + i * 16 + mq + half * 8;
            if (gm < M) {
                #pragma unroll
                for (int j = 0; j < 8; j++) {
                    float2 o = half ? make_float2(acc[i][j][2], acc[i][j][3])
                                    : make_float2(acc[i][j][0], acc[i][j][1]);
                    *reinterpret_cast<float2*>(C + (size_t)gm * CH + nw0 + j * 8 + nq) = o;
                }
            }
        }
    }
}

// ---------------- aggr: aggr[n] = t[n] - min_nbr t[col] ----------------
__global__ void aggr_kernel() {
    const int n = blockIdx.x;
    const int tid = threadIdx.x;
    const int w = tid >> 5;
    const int l = tid & 31;
    const int start = g_off[n];
    const int end = g_off[n + 1];

    __shared__ int s_col[128];
    __shared__ float s_red[4][128];

    float4 m = make_float4(3.402823466e38f, 3.402823466e38f,
                           3.402823466e38f, 3.402823466e38f);

    for (int base = start; base < end; base += 128) {
        int cnt = min(128, end - base);
        if (tid < cnt) s_col[tid] = g_csr[base + tid];
        __syncthreads();
        for (int i = w; i < cnt; i += 4) {
            const float4 v = *reinterpret_cast<const float4*>(
                g_t + (size_t)s_col[i] * CH + l * 4);
            m.x = fminf(m.x, v.x);
            m.y = fminf(m.y, v.y);
            m.z = fminf(m.z, v.z);
            m.w = fminf(m.w, v.w);
        }
        __syncthreads();
    }

    *reinterpret_cast<float4*>(&s_red[w][l * 4]) = m;
    __syncthreads();

    if (w == 0) {
        float4 r = m;
        #pragma unroll
        for (int ww = 1; ww < 4; ww++) {
            float4 o = *reinterpret_cast<const float4*>(&s_red[ww][l * 4]);
            r.x = fminf(r.x, o.x);
            r.y = fminf(r.y, o.y);
            r.z = fminf(r.z, o.z);
            r.w = fminf(r.w, o.w);
        }
        float4 outv;
        if (start == end) {
            outv = make_float4(0.f, 0.f, 0.f, 0.f);
        } else {
            const float4 tv = *reinterpret_cast<const float4*>(
                g_t + (size_t)n * CH + l * 4);
            outv = make_float4(tv.x - r.x, tv.y - r.y, tv.z - r.z, tv.w - r.w);
        }
        *reinterpret_cast<float4*>(g_aggr + (size_t)n * CH + l * 4) = outv;
    }
}

// ---------------- launch ----------------
extern "C" void kernel_launch(void* const* d_in, const int* in_sizes, int n_in,
                              void* d_out, int out_size) {
    const float* x  = (const float*)d_in[0];
    const int*   ei = (const int*)d_in[1];
    const float* Wt = (const float*)d_in[2];
    const float* Wp = (const float*)d_in[3];
    float* out = (float*)d_out;

    int N = in_sizes[0] / CH;
    int E = in_sizes[1] / 2;
    const int* row = ei;
    const int* col = ei + E;
    int nb = (N + SCAN_BLK - 1) / SCAN_BLK;
    int ngb = (N + 127) / 128;

    void *pt = nullptr, *pa = nullptr;
    cudaGetSymbolAddress(&pt, g_t);
    cudaGetSymbolAddress(&pa, g_aggr);

    cudaFuncSetAttribute(tc_gemm_kernel, cudaFuncAttributeMaxDynamicSharedMemorySize, GSM_TOTAL);

    zero_kernel<<<(N + 255) / 256, 256>>>(N);
    conv_w_kernel<<<(2 * CH * CH + 255) / 256, 256>>>(Wt, Wp);
    tc_gemm_kernel<<<ngb, 256, GSM_TOTAL>>>(x, (float*)pt, N, 0);
    count_kernel<<<(E + 255) / 256, 256>>>(row, E);
    scan_block_kernel<<<nb, SCAN_BLK>>>(N);
    scan_top_kernel<<<1, SCAN_BLK>>>(nb, N);
    add_off_kernel<<<nb, SCAN_BLK>>>(N);
    scatter_kernel<<<(E + 255) / 256, 256>>>(row, col, E);
    aggr_kernel<<<N, 128>>>();
    tc_gemm_kernel<<<ngb, 256, GSM_TOTAL>>>((const float*)pa, out, N, 1);
}